// round 1
// baseline (speedup 1.0000x reference)
#include <cuda_runtime.h>
#include <math.h>

#define NN 64
#define TT 512
#define VV 25
#define CIN 3
#define CH 64
#define FF 25
#define GG 100   // 4*F

// Scratch (device globals — no allocation allowed)
__device__ float g_x1[NN * TT * VV * CH];            // (n,t,v,c)   209.7 MB
__device__ float g_z [(size_t)NN * VV * TT * GG];    // (n,v,t,g)   327.7 MB
__device__ float g_h [NN * TT * VV * FF];            // (n,t,v,f)    81.9 MB

// ---------------------------------------------------------------------------
// Kernel 1: x1 = relu(x @ W_conv + b_conv)
// ---------------------------------------------------------------------------
__global__ void conv_kernel(const float* __restrict__ x,
                            const float* __restrict__ Wc,
                            const float* __restrict__ bc) {
    __shared__ float Ws[CIN * CH];
    __shared__ float bs[CH];
    int tid = threadIdx.x;
    if (tid < CIN * CH) Ws[tid] = Wc[tid];
    if (tid < CH)       bs[tid] = bc[tid];
    __syncthreads();

    int e = blockIdx.x * blockDim.x + tid;   // over N*T*V*CH
    int r = e >> 6;          // row (n,t,v)
    int c = e & 63;
    const float* xr = x + r * 3;
    float val = bs[c];
    val = fmaf(xr[0], Ws[c],          val);
    val = fmaf(xr[1], Ws[CH + c],     val);
    val = fmaf(xr[2], Ws[2 * CH + c], val);
    g_x1[e] = fmaxf(val, 0.0f);
}

// ---------------------------------------------------------------------------
// Kernel 2: z = x1 @ W_lstm + b_lstm  -- (819200 x 64) @ (64 x 100)
// Tile: 80 rows x 100 cols per block (320 threads), 5x5 register micro-tile.
// Output stored in (n, v, t, g) layout for contiguous LSTM streaming.
// ---------------------------------------------------------------------------
__global__ __launch_bounds__(320) void zx_kernel(const float* __restrict__ Wl,
                                                 const float* __restrict__ bl) {
    __shared__ float xs[80 * 64];        // 20 KB
    __shared__ float ws[64 * GG];        // 25.6 KB
    __shared__ float bsh[GG];

    int tid  = threadIdx.x;              // 0..319
    int row0 = blockIdx.x * 80;

    for (int i = tid; i < 64 * GG; i += 320) ws[i] = Wl[i];
    if (tid < GG) bsh[tid] = bl[tid];
    for (int i = tid; i < 80 * 64; i += 320) xs[i] = g_x1[row0 * 64 + i];
    __syncthreads();

    int ty = tid / 20;   // 0..15  -> rows ty*5 .. ty*5+4
    int tx = tid % 20;   // 0..19  -> cols tx*5 .. tx*5+4

    float acc[5][5];
#pragma unroll
    for (int i = 0; i < 5; ++i)
#pragma unroll
        for (int j = 0; j < 5; ++j) acc[i][j] = bsh[tx * 5 + j];

#pragma unroll 8
    for (int k = 0; k < 64; ++k) {
        float a[5], b[5];
#pragma unroll
        for (int i = 0; i < 5; ++i) a[i] = xs[(ty * 5 + i) * 64 + k];
#pragma unroll
        for (int j = 0; j < 5; ++j) b[j] = ws[k * GG + tx * 5 + j];
#pragma unroll
        for (int i = 0; i < 5; ++i)
#pragma unroll
            for (int j = 0; j < 5; ++j) acc[i][j] = fmaf(a[i], b[j], acc[i][j]);
    }

#pragma unroll
    for (int i = 0; i < 5; ++i) {
        int row = row0 + ty * 5 + i;           // (n,t,v) flat
        int n   = row / (TT * VV);
        int rem = row % (TT * VV);
        int t   = rem / VV;
        int v   = rem % VV;
        float* zp = g_z + ((size_t)((n * VV + v) * TT + t)) * GG + tx * 5;
#pragma unroll
        for (int j = 0; j < 5; ++j) zp[j] = acc[i][j];
    }
}

// ---------------------------------------------------------------------------
// Kernel 3: sequential LSTM over T. One warp per (n,v) sequence,
// lane j owns hidden unit j (all 4 gates). h broadcast via shfl.
// ---------------------------------------------------------------------------
__device__ __forceinline__ float hsig(float x) {
    return __saturatef(fmaf(0.2f, x, 0.5f));
}

__global__ __launch_bounds__(128) void lstm_kernel(const float* __restrict__ U) {
    __shared__ float Us[FF * GG];   // 25*100 = 10 KB
    int tid = threadIdx.x;
    for (int i = tid; i < FF * GG; i += 128) Us[i] = U[i];
    __syncthreads();

    int warp = blockIdx.x * 4 + (tid >> 5);   // 0..1599
    int lane = tid & 31;
    int n = warp / VV;
    int v = warp % VV;
    int j = (lane < FF) ? lane : 0;           // unit index (lanes >=25 duplicate unit 0)

    const float* zp = g_z + ((size_t)((n * VV + v)) * TT) * GG;
    float* hp = g_h + (n * TT * VV + v) * FF + j;   // stride V*F per step

    float h = 0.0f, c = 0.0f;
    for (int t = 0; t < TT; ++t) {
        float zi = zp[j];
        float zf = zp[FF + j];
        float zg = zp[2 * FF + j];
        float zo = zp[3 * FF + j];
#pragma unroll
        for (int k = 0; k < FF; ++k) {
            float hk = __shfl_sync(0xffffffffu, h, k);
            zi = fmaf(hk, Us[k * GG + j],          zi);
            zf = fmaf(hk, Us[k * GG + FF + j],     zf);
            zg = fmaf(hk, Us[k * GG + 2 * FF + j], zg);
            zo = fmaf(hk, Us[k * GG + 3 * FF + j], zo);
        }
        c = hsig(zf) * c + hsig(zi) * tanhf(zg);
        h = hsig(zo) * tanhf(c);
        if (lane < FF) *hp = h;
        hp += VV * FF;
        zp += GG;
    }
}

// ---------------------------------------------------------------------------
// Kernel 4: coefs = softmax(leaky_relu(h) + bias, axis=-1); out = coefs @ x1
// One block per (n,t).
// ---------------------------------------------------------------------------
__global__ __launch_bounds__(256) void attn_kernel(const float* __restrict__ bias,
                                                   float* __restrict__ out) {
    __shared__ float coefs[VV * VV];   // [v][w]
    __shared__ float x1s[VV * CH];     // [w][c]

    int nt  = blockIdx.x;              // n*T + t
    int tid = threadIdx.x;

    const float* hp = g_h  + nt * VV * FF;
    const float* xp = g_x1 + nt * VV * CH;

    for (int i = tid; i < VV * CH; i += 256) x1s[i] = xp[i];
    for (int i = tid; i < VV * FF; i += 256) {
        float val = hp[i];
        val = (val > 0.0f) ? val : 0.2f * val;   // leaky_relu(0.2)
        coefs[i] = val + bias[i];                 // bias_mat[v][w]
    }
    __syncthreads();

    if (tid < VV) {
        float* row = coefs + tid * VV;
        float m = row[0];
#pragma unroll
        for (int w = 1; w < VV; ++w) m = fmaxf(m, row[w]);
        float s = 0.0f;
#pragma unroll
        for (int w = 0; w < VV; ++w) { float e = __expf(row[w] - m); row[w] = e; s += e; }
        float inv = 1.0f / s;
#pragma unroll
        for (int w = 0; w < VV; ++w) row[w] *= inv;
    }
    __syncthreads();

    float* op = out + nt * VV * CH;
    for (int e = tid; e < VV * CH; e += 256) {
        int v = e >> 6;
        int c = e & 63;
        float acc = 0.0f;
#pragma unroll
        for (int w = 0; w < VV; ++w)
            acc = fmaf(coefs[v * VV + w], x1s[w * CH + c], acc);
        op[e] = acc;
    }
}

// ---------------------------------------------------------------------------
extern "C" void kernel_launch(void* const* d_in, const int* in_sizes, int n_in,
                              void* d_out, int out_size) {
    const float* x     = (const float*)d_in[0];
    const float* Wconv = (const float*)d_in[1];
    const float* bconv = (const float*)d_in[2];
    const float* Wlstm = (const float*)d_in[3];
    const float* Ulstm = (const float*)d_in[4];
    const float* blstm = (const float*)d_in[5];
    const float* bias  = (const float*)d_in[6];
    float* out = (float*)d_out;

    // K1: 52,428,800 elements / 256
    conv_kernel<<<NN * TT * VV * CH / 256, 256>>>(x, Wconv, bconv);
    // K2: 819200 rows / 80 per block
    zx_kernel<<<NN * TT * VV / 80, 320>>>(Wlstm, blstm);
    // K3: 1600 warps, 4 per block
    lstm_kernel<<<NN * VV / 4, 128>>>(Ulstm);
    // K4: one block per (n,t)
    attn_kernel<<<NN * TT, 256>>>(bias, out);
}

// round 2
// speedup vs baseline: 1.1968x; 1.1968x over previous
#include <cuda_runtime.h>
#include <math.h>

#define NN 64
#define TT 512
#define VV 25
#define CIN 3
#define CH 64
#define FF 25
#define GG 100   // 4*F

// Scratch (device globals — no allocation allowed)
__device__ float g_x1[NN * TT * VV * CH];            // (n,t,v,c)
__device__ float g_z [(size_t)NN * VV * TT * GG];    // (n,v,t, j*4+gate)
__device__ float g_h [NN * TT * VV * FF];            // (n,t,v,f)

// ---------------------------------------------------------------------------
// packed f32x2 helpers
// ---------------------------------------------------------------------------
typedef unsigned long long u64t;

__device__ __forceinline__ u64t ffma2(u64t a, u64t b, u64t c) {
    u64t d;
    asm("fma.rn.f32x2 %0, %1, %2, %3;" : "=l"(d) : "l"(a), "l"(b), "l"(c));
    return d;
}
__device__ __forceinline__ u64t pack2(float x, float y) {
    u64t r;
    asm("mov.b64 %0, {%1, %2};" : "=l"(r) : "f"(x), "f"(y));
    return r;
}
__device__ __forceinline__ void unpack2(u64t v, float& x, float& y) {
    asm("mov.b64 {%0, %1}, %2;" : "=f"(x), "=f"(y) : "l"(v));
}
__device__ __forceinline__ float tanhfast(float x) {
    float y;
    asm("tanh.approx.f32 %0, %1;" : "=f"(y) : "f"(x));
    return y;
}
__device__ __forceinline__ float hsig(float x) {
    return __saturatef(fmaf(0.2f, x, 0.5f));
}

// ---------------------------------------------------------------------------
// Kernel 1: x1 = relu(x @ W_conv + b_conv), 4 outputs / thread, float4 store
// ---------------------------------------------------------------------------
__global__ __launch_bounds__(256) void conv_kernel(const float* __restrict__ x,
                                                   const float* __restrict__ Wc,
                                                   const float* __restrict__ bc) {
    __shared__ float Ws[CIN * CH];
    __shared__ float bs[CH];
    int tid = threadIdx.x;
    if (tid < CIN * CH) Ws[tid] = Wc[tid];
    if (tid < CH)       bs[tid] = bc[tid];
    __syncthreads();

    int e  = blockIdx.x * 256 + tid;     // over N*T*V*16
    int r  = e >> 4;                     // row (n,t,v)
    int c0 = (e & 15) << 2;              // channel group of 4
    const float* xr = x + r * 3;
    float x0 = xr[0], x1v = xr[1], x2 = xr[2];
    float4 o;
#pragma unroll
    for (int q = 0; q < 4; ++q) {
        int c = c0 + q;
        float val = bs[c];
        val = fmaf(x0, Ws[c],          val);
        val = fmaf(x1v, Ws[CH + c],    val);
        val = fmaf(x2, Ws[2 * CH + c], val);
        (&o.x)[q] = fmaxf(val, 0.0f);
    }
    *(float4*)(g_x1 + r * CH + c0) = o;
}

// ---------------------------------------------------------------------------
// Kernel 2: z = x1 @ W_lstm + b_lstm  -- (819200 x 64) @ (64 x 100)
// Block: 64 rows x 100 cols, 200 threads. Thread: 8 rows x 1 j (4 gate cols).
// W repacked in smem as float4[(k,j)] = (Wi,Wf,Wg,Wo); packed FFMA2 math.
// Output in gate-interleaved (n,v,t, j*4+gate) layout (float4 stores).
// ---------------------------------------------------------------------------
__global__ __launch_bounds__(200) void zx_kernel(const float* __restrict__ Wl,
                                                 const float* __restrict__ bl) {
    __shared__ float  xs[64 * 65];          // padded rows
    __shared__ float4 ws4[64 * VV];         // (k, j) -> (Wi,Wf,Wg,Wo)
    __shared__ float4 bs4[VV];

    int tid  = threadIdx.x;                 // 0..199
    int row0 = blockIdx.x * 64;

    for (int i = tid; i < 64 * VV; i += 200) {
        int k = i / VV, j = i % VV;
        const float* w = Wl + k * GG + j;
        ws4[i] = make_float4(w[0], w[VV], w[2 * VV], w[3 * VV]);
    }
    if (tid < VV)
        bs4[tid] = make_float4(bl[tid], bl[VV + tid], bl[2 * VV + tid], bl[3 * VV + tid]);
    for (int i = tid; i < 64 * 64; i += 200)
        xs[(i >> 6) * 65 + (i & 63)] = g_x1[(size_t)row0 * 64 + i];
    __syncthreads();

    int ty = tid / VV;   // 0..7  -> rows ty*8 .. ty*8+7
    int j  = tid % VV;   // column group j: cols {j, j+25, j+50, j+75}

    float4 bj = bs4[j];
    u64t accA[8], accB[8];
#pragma unroll
    for (int i = 0; i < 8; ++i) { accA[i] = pack2(bj.x, bj.y); accB[i] = pack2(bj.z, bj.w); }

    const ulonglong2* ws2 = (const ulonglong2*)ws4;
#pragma unroll 4
    for (int k = 0; k < 64; ++k) {
        ulonglong2 b = ws2[k * VV + j];
        u64t a2[8];
#pragma unroll
        for (int i = 0; i < 8; ++i) {
            float a = xs[(ty * 8 + i) * 65 + k];
            a2[i] = pack2(a, a);
        }
#pragma unroll
        for (int i = 0; i < 8; ++i) {
            accA[i] = ffma2(a2[i], b.x, accA[i]);
            accB[i] = ffma2(a2[i], b.y, accB[i]);
        }
    }

#pragma unroll
    for (int i = 0; i < 8; ++i) {
        int row = row0 + ty * 8 + i;           // (n,t,v) flat
        int n   = row / (TT * VV);
        int rem = row % (TT * VV);
        int t   = rem / VV;
        int v   = rem % VV;
        float4 o;
        unpack2(accA[i], o.x, o.y);            // (zi, zf)
        unpack2(accB[i], o.z, o.w);            // (zg, zo)
        size_t base = ((size_t)((n * VV + v) * TT + t)) * GG;
        *(float4*)(g_z + base + j * 4) = o;
    }
}

// ---------------------------------------------------------------------------
// Kernel 3: sequential LSTM. One warp per (n,v) sequence, lane j owns unit j.
// z is gate-interleaved -> 1 LDG.128 per step. U repacked as float4[(k,j)].
// Packed FFMA2 chains for (i,f) and (g,o); tanh.approx for activations.
// ---------------------------------------------------------------------------
__global__ __launch_bounds__(128) void lstm_kernel(const float* __restrict__ U) {
    __shared__ float4 Us4[FF * VV];   // (k, j) -> (Ui,Uf,Ug,Uo), 10 KB
    int tid = threadIdx.x;
    for (int i = tid; i < FF * VV; i += 128) {
        int k = i / VV, j = i % VV;
        const float* u = U + k * GG + j;
        Us4[i] = make_float4(u[0], u[VV], u[2 * VV], u[3 * VV]);
    }
    __syncthreads();

    int warp = blockIdx.x * 4 + (tid >> 5);   // 0..1599
    int lane = tid & 31;
    int n = warp / VV;
    int v = warp % VV;
    int j = (lane < FF) ? lane : 0;

    const float4* zp = (const float4*)(g_z + (size_t)(n * VV + v) * TT * GG) + j;
    float* hp = g_h + ((n * TT) * VV + v) * FF + j;     // + t*VV*FF per step

    const ulonglong2* Us2 = (const ulonglong2*)Us4;

    float h = 0.0f, c = 0.0f;
    float4 zc = zp[0];
    for (int t = 0; t < TT; ++t) {
        float4 zn;
        if (t + 1 < TT) zn = zp[(t + 1) * VV];
        u64t acc_if = pack2(zc.x, zc.y);
        u64t acc_go = pack2(zc.z, zc.w);
#pragma unroll
        for (int k = 0; k < FF; ++k) {
            float hk = __shfl_sync(0xffffffffu, h, k);
            u64t h2 = pack2(hk, hk);
            ulonglong2 u = Us2[k * VV + j];
            acc_if = ffma2(h2, u.x, acc_if);
            acc_go = ffma2(h2, u.y, acc_go);
        }
        float zi, zf, zg, zo;
        unpack2(acc_if, zi, zf);
        unpack2(acc_go, zg, zo);
        c = hsig(zf) * c + hsig(zi) * tanhfast(zg);
        h = hsig(zo) * tanhfast(c);
        if (lane < FF) *hp = h;
        hp += VV * FF;
        zc = zn;
    }
}

// ---------------------------------------------------------------------------
// Kernel 4: coefs = softmax(leaky_relu(h) + bias); out = coefs @ x1
// One block per (n,t). Aggregation: thread owns (v, 8 channels), FFMA2 +
// LDS.128 register blocking.
// ---------------------------------------------------------------------------
__global__ __launch_bounds__(256) void attn_kernel(const float* __restrict__ bias,
                                                   float* __restrict__ out) {
    __shared__ float coefs[VV * VV];                  // [v][w]
    __shared__ __align__(16) float x1s[VV * CH];      // [w][c]

    int nt  = blockIdx.x;              // n*T + t
    int tid = threadIdx.x;

    const float* hp = g_h  + (size_t)nt * VV * FF;
    const float* xp = g_x1 + (size_t)nt * VV * CH;

    for (int i = tid; i < VV * CH / 4; i += 256)
        ((float4*)x1s)[i] = ((const float4*)xp)[i];
    for (int i = tid; i < VV * FF; i += 256) {
        float val = hp[i];
        val = (val > 0.0f) ? val : 0.2f * val;        // leaky_relu(0.2)
        coefs[i] = val + bias[i];
    }
    __syncthreads();

    if (tid < VV) {
        float* row = coefs + tid * VV;
        float m = row[0];
#pragma unroll
        for (int w = 1; w < VV; ++w) m = fmaxf(m, row[w]);
        float s = 0.0f;
#pragma unroll
        for (int w = 0; w < VV; ++w) { float e = __expf(row[w] - m); row[w] = e; s += e; }
        float inv = 1.0f / s;
#pragma unroll
        for (int w = 0; w < VV; ++w) row[w] *= inv;
    }
    __syncthreads();

    if (tid < 200) {
        int v  = tid >> 3;
        int c0 = (tid & 7) << 3;       // 8 channels
        u64t acc[4];
#pragma unroll
        for (int q = 0; q < 4; ++q) acc[q] = pack2(0.0f, 0.0f);
        const float* crow = coefs + v * VV;
#pragma unroll 5
        for (int w = 0; w < VV; ++w) {
            float cf = crow[w];
            u64t c2 = pack2(cf, cf);
            ulonglong2 p0 = *(const ulonglong2*)(x1s + w * CH + c0);
            ulonglong2 p1 = *(const ulonglong2*)(x1s + w * CH + c0 + 4);
            acc[0] = ffma2(c2, p0.x, acc[0]);
            acc[1] = ffma2(c2, p0.y, acc[1]);
            acc[2] = ffma2(c2, p1.x, acc[2]);
            acc[3] = ffma2(c2, p1.y, acc[3]);
        }
        float4 o0, o1;
        unpack2(acc[0], o0.x, o0.y); unpack2(acc[1], o0.z, o0.w);
        unpack2(acc[2], o1.x, o1.y); unpack2(acc[3], o1.z, o1.w);
        float* op = out + (size_t)nt * VV * CH + v * CH + c0;
        *(float4*)op       = o0;
        *(float4*)(op + 4) = o1;
    }
}

// ---------------------------------------------------------------------------
extern "C" void kernel_launch(void* const* d_in, const int* in_sizes, int n_in,
                              void* d_out, int out_size) {
    const float* x     = (const float*)d_in[0];
    const float* Wconv = (const float*)d_in[1];
    const float* bconv = (const float*)d_in[2];
    const float* Wlstm = (const float*)d_in[3];
    const float* Ulstm = (const float*)d_in[4];
    const float* blstm = (const float*)d_in[5];
    const float* bias  = (const float*)d_in[6];
    float* out = (float*)d_out;

    conv_kernel<<<NN * TT * VV * 16 / 256, 256>>>(x, Wconv, bconv);
    zx_kernel  <<<NN * TT * VV / 64, 200>>>(Wlstm, blstm);
    lstm_kernel<<<NN * VV / 4, 128>>>(Ulstm);
    attn_kernel<<<NN * TT, 256>>>(bias, out);
}